// round 1
// baseline (speedup 1.0000x reference)
#include <cuda_runtime.h>
#include <math.h>

#define Bq 64
#define Nn 1024
#define Ee 16384
#define Ff 128
#define Hh 64
#define Tt 10
#define BN (Bq*Nn)   // 65536

// ---------------- scratch (static device globals; no allocs allowed) --------
__device__ float    g_A[BN*Hh];      // linear-transformed features (layer in)
__device__ float    g_Bf[BN*Hh];     // post-layer-1 activations
__device__ int      g_csr[Bq*Ee];    // CSR-by-dst: global src ids
__device__ int      g_off[BN];       // absolute start offset into g_csr
__device__ int      g_indeg[BN];
__device__ unsigned g_mask[BN];      // 10-bit token->node mask
__device__ float    g_invs[BN];      // 1/sqrt(deg_node)
__device__ float    g_invd[BN];      // 1/deg_node
__device__ float    g_st1[Tt*Hh];    // inv_s_tok[t] * (tokens@W1)[t,:]
__device__ float    g_st2[Tt*Hh];    // inv_s_tok[t] * (ht1a@W2)[t,:]
__device__ float    g_toksum[Hh];    // sum_t out_tok2[t,:]
__device__ float    g_emb[Bq*Hh];    // pooled node sums (atomic accum)

// ---------------- token stream: everything T=10-sized in one block ----------
__global__ void token_kernel(const float* __restrict__ tok,
                             const float* __restrict__ W1, const float* __restrict__ b1,
                             const float* __restrict__ W2, const float* __restrict__ b2)
{
    __shared__ float tk[Tt][129];
    __shared__ float nrm[Tt][Tt];
    __shared__ float invsT[Tt], invdT[Tt];
    __shared__ float h1l[Tt][Hh], h1a[Tt][Hh], h2l[Tt][Hh], ot2[Tt][Hh];
    int tid = threadIdx.x;

    for (int i = tid; i < Tt*Ff; i += 128) tk[i/Ff][i%Ff] = tok[i];
    __syncthreads();

    if (tid < Tt*Tt) {                    // M_in bits
        int i = tid/Tt, j = tid%Tt;
        float d = 0.f;
        for (int f = 0; f < Ff; f++) d += tk[i][f]*tk[j][f];
        float s = 1.f/(1.f+expf(-d));
        nrm[i][j] = (s >= 0.3f) ? 1.f : 0.f;
    }
    __syncthreads();
    if (tid < Tt) {                       // deg over columns (targets)
        float deg = 1.f;
        for (int i = 0; i < Tt; i++) deg += nrm[i][tid];
        invsT[tid] = rsqrtf(deg);
        invdT[tid] = 1.f/deg;
    }
    __syncthreads();
    if (tid < Tt*Tt) {                    // norm_in
        int i = tid/Tt, j = tid%Tt;
        nrm[i][j] *= invsT[i]*invsT[j];
    }
    for (int idx = tid; idx < Tt*Hh; idx += 128) {   // ht1_lin = tokens@W1
        int t = idx/Hh, h = idx%Hh;
        float a = 0.f;
        for (int f = 0; f < Ff; f++) a += tk[t][f]*W1[f*Hh+h];
        h1l[t][h] = a;
    }
    __syncthreads();
    for (int idx = tid; idx < Tt*Hh; idx += 128) {   // out_tok1 + lrelu, st1
        int t = idx/Hh, h = idx%Hh;
        float a = h1l[t][h]*invdT[t] + b1[h];
        for (int j = 0; j < Tt; j++) a += nrm[t][j]*h1l[j][h];
        h1a[t][h] = (a >= 0.f) ? a : 0.01f*a;
        g_st1[idx] = invsT[t]*h1l[t][h];
    }
    __syncthreads();
    for (int idx = tid; idx < Tt*Hh; idx += 128) {   // ht2_lin = h1a@W2
        int t = idx/Hh, h = idx%Hh;
        float a = 0.f;
        for (int k = 0; k < Hh; k++) a += h1a[t][k]*W2[k*Hh+h];
        h2l[t][h] = a;
    }
    __syncthreads();
    for (int idx = tid; idx < Tt*Hh; idx += 128) {   // out_tok2, st2
        int t = idx/Hh, h = idx%Hh;
        g_st2[idx] = invsT[t]*h2l[t][h];
        float a = h2l[t][h]*invdT[t] + b2[h];
        for (int j = 0; j < Tt; j++) a += nrm[t][j]*h2l[j][h];
        ot2[t][h] = a;
    }
    __syncthreads();
    if (tid < Hh) {
        float s = 0.f;
        for (int t = 0; t < Tt; t++) s += ot2[t][tid];
        g_toksum[tid] = s;
    }
    for (int i = tid; i < Bq*Hh; i += 128) g_emb[i] = 0.f;   // zero pool accum
}

// ---------------- CSR build: one block per graph (count + scan + scatter) ---
__global__ void csr_kernel(const int* __restrict__ esrc, const int* __restrict__ edst)
{
    __shared__ int cnt[Nn];
    __shared__ int wsum[32];
    int tid = threadIdx.x, b = blockIdx.x;
    int lane = tid & 31, wid = tid >> 5;
    cnt[tid] = 0;
    __syncthreads();
    const int* dp = edst + b*Ee;
    const int* sp = esrc + b*Ee;
    for (int e = tid; e < Ee; e += Nn) atomicAdd(&cnt[dp[e]], 1);
    __syncthreads();
    int c = cnt[tid];
    g_indeg[b*Nn + tid] = c;
    // exclusive scan over 1024 counts
    int v = c;
    for (int d = 1; d < 32; d <<= 1) {
        int u = __shfl_up_sync(0xffffffffu, v, d);
        if (lane >= d) v += u;
    }
    if (lane == 31) wsum[wid] = v;
    __syncthreads();
    if (tid < 32) {
        int u = wsum[tid];
        for (int d = 1; d < 32; d <<= 1) {
            int uu = __shfl_up_sync(0xffffffffu, u, d);
            if (tid >= d) u += uu;
        }
        wsum[tid] = u;
    }
    __syncthreads();
    int base = wid ? wsum[wid-1] : 0;
    int pos0 = b*Ee + base + (v - c);
    g_off[b*Nn + tid] = pos0;
    __syncthreads();
    cnt[tid] = pos0;                      // reuse as scatter cursor
    __syncthreads();
    for (int e = tid; e < Ee; e += Nn) {
        int d = dp[e];
        int p = atomicAdd(&cnt[d], 1);
        g_csr[p] = b*Nn + sp[e];          // store GLOBAL src id
    }
}

// ------- fused x-pass: hn1_lin = x@W1, token dots -> mask, deg finalize -----
__global__ void xpass_kernel(const float* __restrict__ x, const float* __restrict__ W1,
                             const float* __restrict__ tok)
{
    __shared__ float xs[64][68];          // transposed x chunk [f][n]
    __shared__ float ws[64][64];          // W1 chunk [f][h]
    __shared__ float ts[Tt][64];          // tokens chunk [t][f]
    __shared__ unsigned maskbuf[64];
    int tid = threadIdx.x;
    int bn0 = blockIdx.x * 64;
    int h4 = tid & 15, n4 = tid >> 4;

    float4 acc0 = make_float4(0.f,0.f,0.f,0.f);
    float4 acc1 = acc0, acc2 = acc0, acc3 = acc0;
    float dacc[3] = {0.f, 0.f, 0.f};
    if (tid < 64) maskbuf[tid] = 0u;

    for (int c = 0; c < 2; c++) {
        __syncthreads();
        for (int idx = tid; idx < 4096; idx += 256) {
            int f = idx & 63, n = idx >> 6;
            xs[f][n] = x[(bn0+n)*Ff + c*64 + f];
        }
        for (int idx = tid; idx < 4096; idx += 256) {
            int h = idx & 63, f = idx >> 6;
            ws[f][h] = W1[(c*64+f)*Hh + h];
        }
        for (int idx = tid; idx < Tt*64; idx += 256) {
            int f = idx & 63, t = idx >> 6;
            ts[t][f] = tok[t*Ff + c*64 + f];
        }
        __syncthreads();
        #pragma unroll 8
        for (int f = 0; f < 64; f++) {
            float4 xq = *(const float4*)&xs[f][n4*4];
            float4 wq = *(const float4*)&ws[f][h4*4];
            acc0.x += xq.x*wq.x; acc0.y += xq.x*wq.y; acc0.z += xq.x*wq.z; acc0.w += xq.x*wq.w;
            acc1.x += xq.y*wq.x; acc1.y += xq.y*wq.y; acc1.z += xq.y*wq.z; acc1.w += xq.y*wq.w;
            acc2.x += xq.z*wq.x; acc2.y += xq.z*wq.y; acc2.z += xq.z*wq.z; acc2.w += xq.z*wq.w;
            acc3.x += xq.w*wq.x; acc3.y += xq.w*wq.y; acc3.z += xq.w*wq.z; acc3.w += xq.w*wq.w;
        }
        #pragma unroll
        for (int r = 0; r < 3; r++) {
            int idx = tid + r*256;
            if (idx < 640) {
                int n = idx & 63, t = idx >> 6;
                float a = dacc[r];
                #pragma unroll 8
                for (int f = 0; f < 64; f++) a += xs[f][n]*ts[t][f];
                dacc[r] = a;
            }
        }
    }
    #pragma unroll
    for (int r = 0; r < 3; r++) {
        int idx = tid + r*256;
        if (idx < 640) {
            int n = idx & 63, t = idx >> 6;
            float s = 1.f/(1.f+expf(-dacc[r]));
            if (s >= 0.1f) atomicOr(&maskbuf[n], 1u << t);
        }
    }
    __syncthreads();
    {
        int n = n4*4;
        *(float4*)&g_A[(bn0+n+0)*Hh + h4*4] = acc0;
        *(float4*)&g_A[(bn0+n+1)*Hh + h4*4] = acc1;
        *(float4*)&g_A[(bn0+n+2)*Hh + h4*4] = acc2;
        *(float4*)&g_A[(bn0+n+3)*Hh + h4*4] = acc3;
    }
    if (tid < 64) {
        int bn = bn0 + tid;
        unsigned m = maskbuf[tid];
        float deg = 1.0f + (float)g_indeg[bn] + (float)__popc(m);
        g_mask[bn] = m;
        g_invs[bn] = rsqrtf(deg);
        g_invd[bn] = 1.0f/deg;
    }
}

// ---------------- layer-2 linear: g_A = g_Bf @ W2 ---------------------------
__global__ void gemm64_kernel(const float* __restrict__ W2)
{
    __shared__ float xs[64][68];
    __shared__ float ws[64][64];
    int tid = threadIdx.x;
    int bn0 = blockIdx.x * 64;
    int h4 = tid & 15, n4 = tid >> 4;
    for (int idx = tid; idx < 4096; idx += 256) {
        int f = idx & 63, n = idx >> 6;
        xs[f][n] = g_Bf[(bn0+n)*Hh + f];
    }
    for (int idx = tid; idx < 4096; idx += 256) {
        int h = idx & 63, f = idx >> 6;
        ws[f][h] = W2[f*Hh + h];
    }
    __syncthreads();
    float4 acc0 = make_float4(0.f,0.f,0.f,0.f);
    float4 acc1 = acc0, acc2 = acc0, acc3 = acc0;
    #pragma unroll 8
    for (int f = 0; f < 64; f++) {
        float4 xq = *(const float4*)&xs[f][n4*4];
        float4 wq = *(const float4*)&ws[f][h4*4];
        acc0.x += xq.x*wq.x; acc0.y += xq.x*wq.y; acc0.z += xq.x*wq.z; acc0.w += xq.x*wq.w;
        acc1.x += xq.y*wq.x; acc1.y += xq.y*wq.y; acc1.z += xq.y*wq.z; acc1.w += xq.y*wq.w;
        acc2.x += xq.z*wq.x; acc2.y += xq.z*wq.y; acc2.z += xq.z*wq.z; acc2.w += xq.z*wq.w;
        acc3.x += xq.w*wq.x; acc3.y += xq.w*wq.y; acc3.z += xq.w*wq.z; acc3.w += xq.w*wq.w;
    }
    int n = n4*4;
    *(float4*)&g_A[(bn0+n+0)*Hh + h4*4] = acc0;
    *(float4*)&g_A[(bn0+n+1)*Hh + h4*4] = acc1;
    *(float4*)&g_A[(bn0+n+2)*Hh + h4*4] = acc2;
    *(float4*)&g_A[(bn0+n+3)*Hh + h4*4] = acc3;
}

// ---------------- aggregation layer 1 (CSR gather + cross + self + lrelu) ---
__global__ void agg1_kernel(const float* __restrict__ b1)
{
    __shared__ float st[Tt*Hh];
    int tid = threadIdx.x;
    for (int i = tid; i < Tt*Hh; i += 256) st[i] = g_st1[i];
    __syncthreads();
    int lane = tid & 31, w = tid >> 5;
    int bn = blockIdx.x*8 + w;
    int cnt = g_indeg[bn];
    int off = g_off[bn];
    float a0 = 0.f, a1 = 0.f;
    for (int i = 0; i < cnt; i++) {
        int s = g_csr[off + i];
        float wsc = g_invs[s];
        a0 += wsc * g_A[s*Hh + lane];
        a1 += wsc * g_A[s*Hh + 32 + lane];
    }
    unsigned m = g_mask[bn];
    #pragma unroll
    for (int t = 0; t < Tt; t++)
        if ((m >> t) & 1u) { a0 += st[t*Hh + lane]; a1 += st[t*Hh + 32 + lane]; }
    float is = g_invs[bn], id = g_invd[bn];
    float o0 = a0*is + g_A[bn*Hh + lane]*id + b1[lane];
    float o1 = a1*is + g_A[bn*Hh + 32 + lane]*id + b1[32 + lane];
    o0 = (o0 >= 0.f) ? o0 : 0.01f*o0;
    o1 = (o1 >= 0.f) ? o1 : 0.01f*o1;
    g_Bf[bn*Hh + lane] = o0;
    g_Bf[bn*Hh + 32 + lane] = o1;
}

// ---------------- aggregation layer 2 + mean-pool accumulation --------------
__global__ void agg2_kernel(const float* __restrict__ b2)
{
    __shared__ float st[Tt*Hh];
    __shared__ float sum[Hh];
    int tid = threadIdx.x;
    for (int i = tid; i < Tt*Hh; i += 256) st[i] = g_st2[i];
    if (tid < Hh) sum[tid] = 0.f;
    __syncthreads();
    int lane = tid & 31, w = tid >> 5;
    int bn = blockIdx.x*8 + w;
    int cnt = g_indeg[bn];
    int off = g_off[bn];
    float a0 = 0.f, a1 = 0.f;
    for (int i = 0; i < cnt; i++) {
        int s = g_csr[off + i];
        float wsc = g_invs[s];
        a0 += wsc * g_A[s*Hh + lane];
        a1 += wsc * g_A[s*Hh + 32 + lane];
    }
    unsigned m = g_mask[bn];
    #pragma unroll
    for (int t = 0; t < Tt; t++)
        if ((m >> t) & 1u) { a0 += st[t*Hh + lane]; a1 += st[t*Hh + 32 + lane]; }
    float is = g_invs[bn], id = g_invd[bn];
    float o0 = a0*is + g_A[bn*Hh + lane]*id + b2[lane];
    float o1 = a1*is + g_A[bn*Hh + 32 + lane]*id + b2[32 + lane];
    atomicAdd(&sum[lane], o0);
    atomicAdd(&sum[lane + 32], o1);
    __syncthreads();
    if (tid < Hh) {
        int b = (blockIdx.x*8) >> 10;
        atomicAdd(&g_emb[b*Hh + tid], sum[tid]);
    }
}

// ---------------- answering head + softmax ----------------------------------
__global__ void head_kernel(const float* __restrict__ Wa, const float* __restrict__ ba,
                            float* __restrict__ out)
{
    int b = threadIdx.x;
    const float scale = 1.f/(float)(Tt + Nn);
    float l0 = ba[0], l1 = ba[1];
    for (int o = 0; o < Hh; o++) {
        float e = (g_emb[b*Hh + o] + g_toksum[o]) * scale;
        l0 += e*Wa[o*2+0];
        l1 += e*Wa[o*2+1];
    }
    float mx = fmaxf(l0, l1);
    float e0 = expf(l0 - mx), e1 = expf(l1 - mx);
    float s = e0 + e1;
    out[b*2+0] = e0/s;
    out[b*2+1] = e1/s;
}

// ---------------- launch ----------------------------------------------------
extern "C" void kernel_launch(void* const* d_in, const int* in_sizes, int n_in,
                              void* d_out, int out_size)
{
    const float* x    = (const float*)d_in[0];
    const float* tok  = (const float*)d_in[1];
    const float* W1   = (const float*)d_in[2];
    const float* b1   = (const float*)d_in[3];
    const float* W2   = (const float*)d_in[4];
    const float* b2   = (const float*)d_in[5];
    const float* Wa   = (const float*)d_in[6];
    const float* ba   = (const float*)d_in[7];
    const int*   esrc = (const int*)d_in[8];
    const int*   edst = (const int*)d_in[9];
    float* out = (float*)d_out;

    token_kernel<<<1, 128>>>(tok, W1, b1, W2, b2);
    csr_kernel<<<Bq, Nn>>>(esrc, edst);
    xpass_kernel<<<BN/64, 256>>>(x, W1, tok);
    agg1_kernel<<<BN/8, 256>>>(b1);
    gemm64_kernel<<<BN/64, 256>>>(W2);
    agg2_kernel<<<BN/8, 256>>>(b2);
    head_kernel<<<1, Bq>>>(Wa, ba, out);
}

// round 2
// speedup vs baseline: 1.0079x; 1.0079x over previous
#include <cuda_runtime.h>
#include <math.h>

#define Bq 64
#define Nn 1024
#define Ee 16384
#define Ff 128
#define Hh 64
#define Tt 10
#define BN (Bq*Nn)   // 65536

// ---------------- scratch (static device globals; no allocs allowed) --------
__device__ float    g_A[BN*Hh];      // SCALED features: invs[n] * (h @ W)
__device__ float    g_Bf[BN*Hh];     // post-layer-1 activations (unscaled)
__device__ int      g_csr[Bq*Ee];    // CSR-by-dst: global src ids
__device__ int      g_off[BN];       // absolute start offset into g_csr
__device__ int      g_indeg[BN];
__device__ unsigned g_mask[BN];      // 10-bit token->node mask
__device__ float    g_invs[BN];      // 1/sqrt(deg_node)
__device__ float    g_st1[Tt*Hh];    // inv_s_tok[t] * (tokens@W1)[t,:]
__device__ float    g_st2[Tt*Hh];    // inv_s_tok[t] * (ht1a@W2)[t,:]
__device__ float    g_toksum[Hh];    // sum_t out_tok2[t,:]
__device__ float    g_emb[Bq*Hh];    // pooled node sums (atomic accum)

// ---------------- token stream: everything T=10-sized in one block ----------
__global__ void token_kernel(const float* __restrict__ tok,
                             const float* __restrict__ W1, const float* __restrict__ b1,
                             const float* __restrict__ W2, const float* __restrict__ b2)
{
    __shared__ float tk[Tt][129];
    __shared__ float nrm[Tt][Tt];
    __shared__ float invsT[Tt], invdT[Tt];
    __shared__ float h1l[Tt][Hh], h1a[Tt][Hh], h2l[Tt][Hh], ot2[Tt][Hh];
    int tid = threadIdx.x;

    for (int i = tid; i < Tt*Ff; i += 128) tk[i/Ff][i%Ff] = tok[i];
    __syncthreads();

    if (tid < Tt*Tt) {                    // M_in bits
        int i = tid/Tt, j = tid%Tt;
        float d = 0.f;
        for (int f = 0; f < Ff; f++) d += tk[i][f]*tk[j][f];
        float s = 1.f/(1.f+expf(-d));
        nrm[i][j] = (s >= 0.3f) ? 1.f : 0.f;
    }
    __syncthreads();
    if (tid < Tt) {                       // deg over columns (targets)
        float deg = 1.f;
        for (int i = 0; i < Tt; i++) deg += nrm[i][tid];
        invsT[tid] = rsqrtf(deg);
        invdT[tid] = 1.f/deg;
    }
    __syncthreads();
    if (tid < Tt*Tt) {                    // norm_in
        int i = tid/Tt, j = tid%Tt;
        nrm[i][j] *= invsT[i]*invsT[j];
    }
    for (int idx = tid; idx < Tt*Hh; idx += 128) {   // ht1_lin = tokens@W1
        int t = idx/Hh, h = idx%Hh;
        float a = 0.f;
        for (int f = 0; f < Ff; f++) a += tk[t][f]*W1[f*Hh+h];
        h1l[t][h] = a;
    }
    __syncthreads();
    for (int idx = tid; idx < Tt*Hh; idx += 128) {   // out_tok1 + lrelu, st1
        int t = idx/Hh, h = idx%Hh;
        float a = h1l[t][h]*invdT[t] + b1[h];
        for (int j = 0; j < Tt; j++) a += nrm[t][j]*h1l[j][h];
        h1a[t][h] = (a >= 0.f) ? a : 0.01f*a;
        g_st1[idx] = invsT[t]*h1l[t][h];
    }
    __syncthreads();
    for (int idx = tid; idx < Tt*Hh; idx += 128) {   // ht2_lin = h1a@W2
        int t = idx/Hh, h = idx%Hh;
        float a = 0.f;
        for (int k = 0; k < Hh; k++) a += h1a[t][k]*W2[k*Hh+h];
        h2l[t][h] = a;
    }
    __syncthreads();
    for (int idx = tid; idx < Tt*Hh; idx += 128) {   // out_tok2, st2
        int t = idx/Hh, h = idx%Hh;
        g_st2[idx] = invsT[t]*h2l[t][h];
        float a = h2l[t][h]*invdT[t] + b2[h];
        for (int j = 0; j < Tt; j++) a += nrm[t][j]*h2l[j][h];
        ot2[t][h] = a;
    }
    __syncthreads();
    if (tid < Hh) {
        float s = 0.f;
        for (int t = 0; t < Tt; t++) s += ot2[t][tid];
        g_toksum[tid] = s;
    }
    for (int i = tid; i < Bq*Hh; i += 128) g_emb[i] = 0.f;   // zero pool accum
}

// ---------------- CSR build: one block per graph (count + scan + scatter) ---
__global__ void csr_kernel(const int* __restrict__ esrc, const int* __restrict__ edst)
{
    __shared__ int cnt[Nn];
    __shared__ int wsum[32];
    int tid = threadIdx.x, b = blockIdx.x;
    int lane = tid & 31, wid = tid >> 5;
    cnt[tid] = 0;
    __syncthreads();
    const int* dp = edst + b*Ee;
    const int* sp = esrc + b*Ee;
    for (int e = tid; e < Ee; e += Nn) atomicAdd(&cnt[dp[e]], 1);
    __syncthreads();
    int c = cnt[tid];
    g_indeg[b*Nn + tid] = c;
    // exclusive scan over 1024 counts
    int v = c;
    for (int d = 1; d < 32; d <<= 1) {
        int u = __shfl_up_sync(0xffffffffu, v, d);
        if (lane >= d) v += u;
    }
    if (lane == 31) wsum[wid] = v;
    __syncthreads();
    if (tid < 32) {
        int u = wsum[tid];
        for (int d = 1; d < 32; d <<= 1) {
            int uu = __shfl_up_sync(0xffffffffu, u, d);
            if (tid >= d) u += uu;
        }
        wsum[tid] = u;
    }
    __syncthreads();
    int base = wid ? wsum[wid-1] : 0;
    int pos0 = b*Ee + base + (v - c);
    g_off[b*Nn + tid] = pos0;
    __syncthreads();
    cnt[tid] = pos0;                      // reuse as scatter cursor
    __syncthreads();
    for (int e = tid; e < Ee; e += Nn) {
        int d = dp[e];
        int p = atomicAdd(&cnt[d], 1);
        g_csr[p] = b*Nn + sp[e];          // store GLOBAL src id
    }
}

// ------- fused x-pass: As1 = invs*(x@W1), token dots -> mask, deg finalize --
__global__ void xpass_kernel(const float* __restrict__ x, const float* __restrict__ W1,
                             const float* __restrict__ tok)
{
    __shared__ float xs[64][68];          // transposed x chunk [f][n]
    __shared__ float ws[64][64];          // W1 chunk [f][h]
    __shared__ float ts[Tt][64];          // tokens chunk [t][f]
    __shared__ unsigned maskbuf[64];
    __shared__ float invsS[64];
    int tid = threadIdx.x;
    int bn0 = blockIdx.x * 64;
    int h4 = tid & 15, n4 = tid >> 4;

    float4 acc0 = make_float4(0.f,0.f,0.f,0.f);
    float4 acc1 = acc0, acc2 = acc0, acc3 = acc0;
    float dacc[3] = {0.f, 0.f, 0.f};
    if (tid < 64) maskbuf[tid] = 0u;

    for (int c = 0; c < 2; c++) {
        __syncthreads();
        for (int idx = tid; idx < 4096; idx += 256) {
            int f = idx & 63, n = idx >> 6;
            xs[f][n] = x[(bn0+n)*Ff + c*64 + f];
        }
        for (int idx = tid; idx < 4096; idx += 256) {
            int h = idx & 63, f = idx >> 6;
            ws[f][h] = W1[(c*64+f)*Hh + h];
        }
        for (int idx = tid; idx < Tt*64; idx += 256) {
            int f = idx & 63, t = idx >> 6;
            ts[t][f] = tok[t*Ff + c*64 + f];
        }
        __syncthreads();
        #pragma unroll 8
        for (int f = 0; f < 64; f++) {
            float4 xq = *(const float4*)&xs[f][n4*4];
            float4 wq = *(const float4*)&ws[f][h4*4];
            acc0.x += xq.x*wq.x; acc0.y += xq.x*wq.y; acc0.z += xq.x*wq.z; acc0.w += xq.x*wq.w;
            acc1.x += xq.y*wq.x; acc1.y += xq.y*wq.y; acc1.z += xq.y*wq.z; acc1.w += xq.y*wq.w;
            acc2.x += xq.z*wq.x; acc2.y += xq.z*wq.y; acc2.z += xq.z*wq.z; acc2.w += xq.z*wq.w;
            acc3.x += xq.w*wq.x; acc3.y += xq.w*wq.y; acc3.z += xq.w*wq.z; acc3.w += xq.w*wq.w;
        }
        #pragma unroll
        for (int r = 0; r < 3; r++) {
            int idx = tid + r*256;
            if (idx < 640) {
                int n = idx & 63, t = idx >> 6;
                float a = dacc[r];
                #pragma unroll 8
                for (int f = 0; f < 64; f++) a += xs[f][n]*ts[t][f];
                dacc[r] = a;
            }
        }
    }
    #pragma unroll
    for (int r = 0; r < 3; r++) {
        int idx = tid + r*256;
        if (idx < 640) {
            int n = idx & 63, t = idx >> 6;
            float s = 1.f/(1.f+expf(-dacc[r]));
            if (s >= 0.1f) atomicOr(&maskbuf[n], 1u << t);
        }
    }
    __syncthreads();
    if (tid < 64) {                       // finalize degree -> invs
        int bn = bn0 + tid;
        unsigned m = maskbuf[tid];
        float deg = 1.0f + (float)g_indeg[bn] + (float)__popc(m);
        float is = rsqrtf(deg);
        g_mask[bn] = m;
        g_invs[bn] = is;
        invsS[tid] = is;
    }
    __syncthreads();
    {   // store rows pre-scaled by invs
        int n = n4*4;
        float s0 = invsS[n], s1 = invsS[n+1], s2 = invsS[n+2], s3 = invsS[n+3];
        acc0.x*=s0; acc0.y*=s0; acc0.z*=s0; acc0.w*=s0;
        acc1.x*=s1; acc1.y*=s1; acc1.z*=s1; acc1.w*=s1;
        acc2.x*=s2; acc2.y*=s2; acc2.z*=s2; acc2.w*=s2;
        acc3.x*=s3; acc3.y*=s3; acc3.z*=s3; acc3.w*=s3;
        *(float4*)&g_A[(bn0+n+0)*Hh + h4*4] = acc0;
        *(float4*)&g_A[(bn0+n+1)*Hh + h4*4] = acc1;
        *(float4*)&g_A[(bn0+n+2)*Hh + h4*4] = acc2;
        *(float4*)&g_A[(bn0+n+3)*Hh + h4*4] = acc3;
    }
}

// ---------------- layer-2 linear: g_A = invs * (g_Bf @ W2) ------------------
__global__ void gemm64_kernel(const float* __restrict__ W2)
{
    __shared__ float xs[64][68];
    __shared__ float ws[64][64];
    int tid = threadIdx.x;
    int bn0 = blockIdx.x * 64;
    int h4 = tid & 15, n4 = tid >> 4;
    for (int idx = tid; idx < 4096; idx += 256) {
        int f = idx & 63, n = idx >> 6;
        xs[f][n] = g_Bf[(bn0+n)*Hh + f];
    }
    for (int idx = tid; idx < 4096; idx += 256) {
        int h = idx & 63, f = idx >> 6;
        ws[f][h] = W2[f*Hh + h];
    }
    __syncthreads();
    float4 acc0 = make_float4(0.f,0.f,0.f,0.f);
    float4 acc1 = acc0, acc2 = acc0, acc3 = acc0;
    #pragma unroll 8
    for (int f = 0; f < 64; f++) {
        float4 xq = *(const float4*)&xs[f][n4*4];
        float4 wq = *(const float4*)&ws[f][h4*4];
        acc0.x += xq.x*wq.x; acc0.y += xq.x*wq.y; acc0.z += xq.x*wq.z; acc0.w += xq.x*wq.w;
        acc1.x += xq.y*wq.x; acc1.y += xq.y*wq.y; acc1.z += xq.y*wq.z; acc1.w += xq.y*wq.w;
        acc2.x += xq.z*wq.x; acc2.y += xq.z*wq.y; acc2.z += xq.z*wq.z; acc2.w += xq.z*wq.w;
        acc3.x += xq.w*wq.x; acc3.y += xq.w*wq.y; acc3.z += xq.w*wq.z; acc3.w += xq.w*wq.w;
    }
    int n = n4*4;
    float s0 = g_invs[bn0+n], s1 = g_invs[bn0+n+1], s2 = g_invs[bn0+n+2], s3 = g_invs[bn0+n+3];
    acc0.x*=s0; acc0.y*=s0; acc0.z*=s0; acc0.w*=s0;
    acc1.x*=s1; acc1.y*=s1; acc1.z*=s1; acc1.w*=s1;
    acc2.x*=s2; acc2.y*=s2; acc2.z*=s2; acc2.w*=s2;
    acc3.x*=s3; acc3.y*=s3; acc3.z*=s3; acc3.w*=s3;
    *(float4*)&g_A[(bn0+n+0)*Hh + h4*4] = acc0;
    *(float4*)&g_A[(bn0+n+1)*Hh + h4*4] = acc1;
    *(float4*)&g_A[(bn0+n+2)*Hh + h4*4] = acc2;
    *(float4*)&g_A[(bn0+n+3)*Hh + h4*4] = acc3;
}

// ------- aggregation layer 1: pure gather of pre-scaled rows + lrelu --------
__global__ void agg1_kernel(const float* __restrict__ b1)
{
    __shared__ float2 st[Tt*32];
    __shared__ float2 bias[32];
    int tid = threadIdx.x;
    const float2* s1p = (const float2*)g_st1;
    for (int i = tid; i < Tt*32; i += 256) st[i] = s1p[i];
    if (tid < 32) bias[tid] = ((const float2*)b1)[tid];
    __syncthreads();
    int lane = tid & 31;
    int bn = blockIdx.x*8 + (tid >> 5);
    const float2* A2 = (const float2*)g_A;
    int cnt = g_indeg[bn];
    int off = g_off[bn];
    float2 acc = make_float2(0.f, 0.f);
    for (int base = 0; base < cnt; base += 32) {
        int rem = cnt - base;
        int m = rem < 32 ? rem : 32;
        int idx = g_csr[off + base + (lane < m ? lane : 0)];
        int j = 0;
        for (; j + 4 <= m; j += 4) {
            int s0 = __shfl_sync(0xffffffffu, idx, j);
            int s1 = __shfl_sync(0xffffffffu, idx, j+1);
            int s2 = __shfl_sync(0xffffffffu, idx, j+2);
            int s3 = __shfl_sync(0xffffffffu, idx, j+3);
            float2 v0 = A2[s0*32 + lane];
            float2 v1 = A2[s1*32 + lane];
            float2 v2 = A2[s2*32 + lane];
            float2 v3 = A2[s3*32 + lane];
            acc.x += (v0.x + v1.x) + (v2.x + v3.x);
            acc.y += (v0.y + v1.y) + (v2.y + v3.y);
        }
        for (; j < m; j++) {
            int s = __shfl_sync(0xffffffffu, idx, j);
            float2 v = A2[s*32 + lane];
            acc.x += v.x; acc.y += v.y;
        }
    }
    unsigned mk = g_mask[bn];
    while (mk) {
        int t = __ffs(mk) - 1; mk &= mk - 1;
        float2 v = st[t*32 + lane];
        acc.x += v.x; acc.y += v.y;
    }
    float2 self = A2[bn*32 + lane];
    acc.x += self.x; acc.y += self.y;
    float is = g_invs[bn];
    float2 bb = bias[lane];
    float o0 = acc.x*is + bb.x;
    float o1 = acc.y*is + bb.y;
    o0 = (o0 >= 0.f) ? o0 : 0.01f*o0;
    o1 = (o1 >= 0.f) ? o1 : 0.01f*o1;
    ((float2*)g_Bf)[bn*32 + lane] = make_float2(o0, o1);
}

// ------- aggregation layer 2 + mean-pool accumulation -----------------------
__global__ void agg2_kernel(const float* __restrict__ b2)
{
    __shared__ float2 st[Tt*32];
    __shared__ float2 bias[32];
    __shared__ float sum[Hh];
    int tid = threadIdx.x;
    const float2* s2p = (const float2*)g_st2;
    for (int i = tid; i < Tt*32; i += 256) st[i] = s2p[i];
    if (tid < 32) bias[tid] = ((const float2*)b2)[tid];
    if (tid < Hh) sum[tid] = 0.f;
    __syncthreads();
    int lane = tid & 31;
    int bn = blockIdx.x*8 + (tid >> 5);
    const float2* A2 = (const float2*)g_A;
    int cnt = g_indeg[bn];
    int off = g_off[bn];
    float2 acc = make_float2(0.f, 0.f);
    for (int base = 0; base < cnt; base += 32) {
        int rem = cnt - base;
        int m = rem < 32 ? rem : 32;
        int idx = g_csr[off + base + (lane < m ? lane : 0)];
        int j = 0;
        for (; j + 4 <= m; j += 4) {
            int s0 = __shfl_sync(0xffffffffu, idx, j);
            int s1 = __shfl_sync(0xffffffffu, idx, j+1);
            int s2 = __shfl_sync(0xffffffffu, idx, j+2);
            int s3 = __shfl_sync(0xffffffffu, idx, j+3);
            float2 v0 = A2[s0*32 + lane];
            float2 v1 = A2[s1*32 + lane];
            float2 v2 = A2[s2*32 + lane];
            float2 v3 = A2[s3*32 + lane];
            acc.x += (v0.x + v1.x) + (v2.x + v3.x);
            acc.y += (v0.y + v1.y) + (v2.y + v3.y);
        }
        for (; j < m; j++) {
            int s = __shfl_sync(0xffffffffu, idx, j);
            float2 v = A2[s*32 + lane];
            acc.x += v.x; acc.y += v.y;
        }
    }
    unsigned mk = g_mask[bn];
    while (mk) {
        int t = __ffs(mk) - 1; mk &= mk - 1;
        float2 v = st[t*32 + lane];
        acc.x += v.x; acc.y += v.y;
    }
    float2 self = A2[bn*32 + lane];
    acc.x += self.x; acc.y += self.y;
    float is = g_invs[bn];
    float2 bb = bias[lane];
    float o0 = acc.x*is + bb.x;
    float o1 = acc.y*is + bb.y;
    atomicAdd(&sum[2*lane], o0);
    atomicAdd(&sum[2*lane+1], o1);
    __syncthreads();
    if (tid < Hh) {
        int b = (blockIdx.x*8) >> 10;
        atomicAdd(&g_emb[b*Hh + tid], sum[tid]);
    }
}

// ---------------- answering head + softmax ----------------------------------
__global__ void head_kernel(const float* __restrict__ Wa, const float* __restrict__ ba,
                            float* __restrict__ out)
{
    int b = threadIdx.x;
    const float scale = 1.f/(float)(Tt + Nn);
    float l0 = ba[0], l1 = ba[1];
    for (int o = 0; o < Hh; o++) {
        float e = (g_emb[b*Hh + o] + g_toksum[o]) * scale;
        l0 += e*Wa[o*2+0];
        l1 += e*Wa[o*2+1];
    }
    float mx = fmaxf(l0, l1);
    float e0 = expf(l0 - mx), e1 = expf(l1 - mx);
    float s = e0 + e1;
    out[b*2+0] = e0/s;
    out[b*2+1] = e1/s;
}

// ---------------- launch ----------------------------------------------------
extern "C" void kernel_launch(void* const* d_in, const int* in_sizes, int n_in,
                              void* d_out, int out_size)
{
    const float* x    = (const float*)d_in[0];
    const float* tok  = (const float*)d_in[1];
    const float* W1   = (const float*)d_in[2];
    const float* b1   = (const float*)d_in[3];
    const float* W2   = (const float*)d_in[4];
    const float* b2   = (const float*)d_in[5];
    const float* Wa   = (const float*)d_in[6];
    const float* ba   = (const float*)d_in[7];
    const int*   esrc = (const int*)d_in[8];
    const int*   edst = (const int*)d_in[9];
    float* out = (float*)d_out;

    token_kernel<<<1, 128>>>(tok, W1, b1, W2, b2);
    csr_kernel<<<Bq, Nn>>>(esrc, edst);
    xpass_kernel<<<BN/64, 256>>>(x, W1, tok);
    agg1_kernel<<<BN/8, 256>>>(b1);
    gemm64_kernel<<<BN/64, 256>>>(W2);
    agg2_kernel<<<BN/8, 256>>>(b2);
    head_kernel<<<1, Bq>>>(Wa, ba, out);
}

// round 3
// speedup vs baseline: 1.1549x; 1.1459x over previous
#include <cuda_runtime.h>
#include <cuda_bf16.h>
#include <math.h>

#define Bq 64
#define Nn 1024
#define Ee 16384
#define Ff 128
#define Hh 64
#define Tt 10
#define BN (Bq*Nn)   // 65536

// ---------------- scratch (static device globals; no allocs allowed) --------
__device__ __nv_bfloat16 g_A[BN*Hh]; // SCALED features in bf16: invs[n]*(h@W)
__device__ float    g_Bf[BN*Hh];     // post-layer-1 activations (fp32)
__device__ int      g_csr[Bq*Ee];    // CSR-by-dst: global src ids
__device__ int      g_off[BN];       // absolute start offset into g_csr
__device__ int      g_indeg[BN];
__device__ unsigned g_mask[BN];      // 10-bit token->node mask
__device__ float    g_invs[BN];      // 1/sqrt(deg_node)
__device__ float    g_st1[Tt*Hh];    // inv_s_tok[t] * (tokens@W1)[t,:]
__device__ float    g_st2[Tt*Hh];    // inv_s_tok[t] * (ht1a@W2)[t,:]
__device__ float    g_toksum[Hh];    // sum_t out_tok2[t,:]
__device__ float    g_emb[Bq*Hh];    // pooled node sums (atomic accum)

// ---- helpers ----------------------------------------------------------------
__device__ __forceinline__ void acc_bf16x4(float4& a, uint2 v) {
    __nv_bfloat162 p0 = *reinterpret_cast<__nv_bfloat162*>(&v.x);
    __nv_bfloat162 p1 = *reinterpret_cast<__nv_bfloat162*>(&v.y);
    float2 f0 = __bfloat1622float2(p0);
    float2 f1 = __bfloat1622float2(p1);
    a.x += f0.x; a.y += f0.y; a.z += f1.x; a.w += f1.y;
}
__device__ __forceinline__ uint2 pack_bf16x4(float4 a) {
    __nv_bfloat162 lo = __float22bfloat162_rn(make_float2(a.x, a.y));
    __nv_bfloat162 hi = __float22bfloat162_rn(make_float2(a.z, a.w));
    uint2 r;
    r.x = *reinterpret_cast<unsigned*>(&lo);
    r.y = *reinterpret_cast<unsigned*>(&hi);
    return r;
}

// ---------------- CSR build (blocks 0-63) + token stream (block 64) ---------
__global__ void csr_token_kernel(const int* __restrict__ esrc, const int* __restrict__ edst,
                                 const float* __restrict__ tok,
                                 const float* __restrict__ W1, const float* __restrict__ b1,
                                 const float* __restrict__ W2, const float* __restrict__ b2)
{
    __shared__ union {
        struct { int cnt[Nn]; int wsum[32]; } c;
        struct {
            float tk[Tt][129];
            float nrm[Tt][Tt];
            float invsT[Tt], invdT[Tt];
            float h1l[Tt][Hh], h1a[Tt][Hh], h2l[Tt][Hh], ot2[Tt][Hh];
        } t;
    } u;
    int tid = threadIdx.x;

    if (blockIdx.x < Bq) {
        // ---------------- CSR build: count + scan + scatter -----------------
        int b = blockIdx.x;
        int lane = tid & 31, wid = tid >> 5;
        u.c.cnt[tid] = 0;
        __syncthreads();
        const int* dp = edst + b*Ee;
        const int* sp = esrc + b*Ee;
        for (int e = tid; e < Ee; e += Nn) atomicAdd(&u.c.cnt[dp[e]], 1);
        __syncthreads();
        int c = u.c.cnt[tid];
        g_indeg[b*Nn + tid] = c;
        int v = c;
        for (int d = 1; d < 32; d <<= 1) {
            int uu = __shfl_up_sync(0xffffffffu, v, d);
            if (lane >= d) v += uu;
        }
        if (lane == 31) u.c.wsum[wid] = v;
        __syncthreads();
        if (tid < 32) {
            int s = u.c.wsum[tid];
            for (int d = 1; d < 32; d <<= 1) {
                int uu = __shfl_up_sync(0xffffffffu, s, d);
                if (tid >= d) s += uu;
            }
            u.c.wsum[tid] = s;
        }
        __syncthreads();
        int base = wid ? u.c.wsum[wid-1] : 0;
        int pos0 = b*Ee + base + (v - c);
        g_off[b*Nn + tid] = pos0;
        __syncthreads();
        u.c.cnt[tid] = pos0;
        __syncthreads();
        for (int e = tid; e < Ee; e += Nn) {
            int d = dp[e];
            int p = atomicAdd(&u.c.cnt[d], 1);
            g_csr[p] = b*Nn + sp[e];
        }
    } else {
        // ---------------- token stream (T=10) -------------------------------
        const int NT = 1024;
        for (int i = tid; i < Tt*Ff; i += NT) u.t.tk[i/Ff][i%Ff] = tok[i];
        __syncthreads();
        if (tid < Tt*Tt) {
            int i = tid/Tt, j = tid%Tt;
            float d = 0.f;
            for (int f = 0; f < Ff; f++) d += u.t.tk[i][f]*u.t.tk[j][f];
            float s = 1.f/(1.f+expf(-d));
            u.t.nrm[i][j] = (s >= 0.3f) ? 1.f : 0.f;
        }
        __syncthreads();
        if (tid < Tt) {
            float deg = 1.f;
            for (int i = 0; i < Tt; i++) deg += u.t.nrm[i][tid];
            u.t.invsT[tid] = rsqrtf(deg);
            u.t.invdT[tid] = 1.f/deg;
        }
        __syncthreads();
        if (tid < Tt*Tt) {
            int i = tid/Tt, j = tid%Tt;
            u.t.nrm[i][j] *= u.t.invsT[i]*u.t.invsT[j];
        }
        for (int idx = tid; idx < Tt*Hh; idx += NT) {
            int t = idx/Hh, h = idx%Hh;
            float a = 0.f;
            for (int f = 0; f < Ff; f++) a += u.t.tk[t][f]*W1[f*Hh+h];
            u.t.h1l[t][h] = a;
        }
        __syncthreads();
        for (int idx = tid; idx < Tt*Hh; idx += NT) {
            int t = idx/Hh, h = idx%Hh;
            float a = u.t.h1l[t][h]*u.t.invdT[t] + b1[h];
            for (int j = 0; j < Tt; j++) a += u.t.nrm[t][j]*u.t.h1l[j][h];
            u.t.h1a[t][h] = (a >= 0.f) ? a : 0.01f*a;
            g_st1[idx] = u.t.invsT[t]*u.t.h1l[t][h];
        }
        __syncthreads();
        for (int idx = tid; idx < Tt*Hh; idx += NT) {
            int t = idx/Hh, h = idx%Hh;
            float a = 0.f;
            for (int k = 0; k < Hh; k++) a += u.t.h1a[t][k]*W2[k*Hh+h];
            u.t.h2l[t][h] = a;
        }
        __syncthreads();
        for (int idx = tid; idx < Tt*Hh; idx += NT) {
            int t = idx/Hh, h = idx%Hh;
            g_st2[idx] = u.t.invsT[t]*u.t.h2l[t][h];
            float a = u.t.h2l[t][h]*u.t.invdT[t] + b2[h];
            for (int j = 0; j < Tt; j++) a += u.t.nrm[t][j]*u.t.h2l[j][h];
            u.t.ot2[t][h] = a;
        }
        __syncthreads();
        if (tid < Hh) {
            float s = 0.f;
            for (int t = 0; t < Tt; t++) s += u.t.ot2[t][tid];
            g_toksum[tid] = s;
        }
        for (int i = tid; i < Bq*Hh; i += NT) g_emb[i] = 0.f;
    }
}

// ------- fused x-pass: As1 = bf16(invs*(x@W1)), token dots -> mask, deg -----
__global__ void xpass_kernel(const float* __restrict__ x, const float* __restrict__ W1,
                             const float* __restrict__ tok)
{
    __shared__ float xs[64][68];          // transposed x chunk [f][n]
    __shared__ float ws[64][64];          // W1 chunk [f][h]
    __shared__ float ts[Tt][64];          // tokens chunk [t][f]
    __shared__ unsigned maskbuf[64];
    __shared__ float invsS[64];
    int tid = threadIdx.x;
    int bn0 = blockIdx.x * 64;
    int h4 = tid & 15, n4 = tid >> 4;

    float4 acc0 = make_float4(0.f,0.f,0.f,0.f);
    float4 acc1 = acc0, acc2 = acc0, acc3 = acc0;
    float dacc[3] = {0.f, 0.f, 0.f};
    if (tid < 64) maskbuf[tid] = 0u;

    for (int c = 0; c < 2; c++) {
        __syncthreads();
        for (int idx = tid; idx < 4096; idx += 256) {
            int f = idx & 63, n = idx >> 6;
            xs[f][n] = x[(bn0+n)*Ff + c*64 + f];
        }
        for (int idx = tid; idx < 4096; idx += 256) {
            int h = idx & 63, f = idx >> 6;
            ws[f][h] = W1[(c*64+f)*Hh + h];
        }
        for (int idx = tid; idx < Tt*64; idx += 256) {
            int f = idx & 63, t = idx >> 6;
            ts[t][f] = tok[t*Ff + c*64 + f];
        }
        __syncthreads();
        #pragma unroll 8
        for (int f = 0; f < 64; f++) {
            float4 xq = *(const float4*)&xs[f][n4*4];
            float4 wq = *(const float4*)&ws[f][h4*4];
            acc0.x += xq.x*wq.x; acc0.y += xq.x*wq.y; acc0.z += xq.x*wq.z; acc0.w += xq.x*wq.w;
            acc1.x += xq.y*wq.x; acc1.y += xq.y*wq.y; acc1.z += xq.y*wq.z; acc1.w += xq.y*wq.w;
            acc2.x += xq.z*wq.x; acc2.y += xq.z*wq.y; acc2.z += xq.z*wq.z; acc2.w += xq.z*wq.w;
            acc3.x += xq.w*wq.x; acc3.y += xq.w*wq.y; acc3.z += xq.w*wq.z; acc3.w += xq.w*wq.w;
        }
        #pragma unroll
        for (int r = 0; r < 3; r++) {
            int idx = tid + r*256;
            if (idx < 640) {
                int n = idx & 63, t = idx >> 6;
                float a = dacc[r];
                #pragma unroll 8
                for (int f = 0; f < 64; f++) a += xs[f][n]*ts[t][f];
                dacc[r] = a;
            }
        }
    }
    #pragma unroll
    for (int r = 0; r < 3; r++) {
        int idx = tid + r*256;
        if (idx < 640) {
            int n = idx & 63, t = idx >> 6;
            float s = 1.f/(1.f+expf(-dacc[r]));
            if (s >= 0.1f) atomicOr(&maskbuf[n], 1u << t);
        }
    }
    __syncthreads();
    if (tid < 64) {
        int bn = bn0 + tid;
        unsigned m = maskbuf[tid];
        float deg = 1.0f + (float)g_indeg[bn] + (float)__popc(m);
        float is = rsqrtf(deg);
        g_mask[bn] = m;
        g_invs[bn] = is;
        invsS[tid] = is;
    }
    __syncthreads();
    {
        int n = n4*4;
        float s0 = invsS[n], s1 = invsS[n+1], s2 = invsS[n+2], s3 = invsS[n+3];
        acc0.x*=s0; acc0.y*=s0; acc0.z*=s0; acc0.w*=s0;
        acc1.x*=s1; acc1.y*=s1; acc1.z*=s1; acc1.w*=s1;
        acc2.x*=s2; acc2.y*=s2; acc2.z*=s2; acc2.w*=s2;
        acc3.x*=s3; acc3.y*=s3; acc3.z*=s3; acc3.w*=s3;
        uint2* A2 = (uint2*)g_A;
        A2[(bn0+n+0)*16 + h4] = pack_bf16x4(acc0);
        A2[(bn0+n+1)*16 + h4] = pack_bf16x4(acc1);
        A2[(bn0+n+2)*16 + h4] = pack_bf16x4(acc2);
        A2[(bn0+n+3)*16 + h4] = pack_bf16x4(acc3);
    }
}

// ---------------- layer-2 linear: g_A = bf16(invs * (g_Bf @ W2)) ------------
__global__ void gemm64_kernel(const float* __restrict__ W2)
{
    __shared__ float xs[64][68];
    __shared__ float ws[64][64];
    int tid = threadIdx.x;
    int bn0 = blockIdx.x * 64;
    int h4 = tid & 15, n4 = tid >> 4;
    for (int idx = tid; idx < 4096; idx += 256) {
        int f = idx & 63, n = idx >> 6;
        xs[f][n] = g_Bf[(bn0+n)*Hh + f];
    }
    for (int idx = tid; idx < 4096; idx += 256) {
        int h = idx & 63, f = idx >> 6;
        ws[f][h] = W2[f*Hh + h];
    }
    __syncthreads();
    float4 acc0 = make_float4(0.f,0.f,0.f,0.f);
    float4 acc1 = acc0, acc2 = acc0, acc3 = acc0;
    #pragma unroll 8
    for (int f = 0; f < 64; f++) {
        float4 xq = *(const float4*)&xs[f][n4*4];
        float4 wq = *(const float4*)&ws[f][h4*4];
        acc0.x += xq.x*wq.x; acc0.y += xq.x*wq.y; acc0.z += xq.x*wq.z; acc0.w += xq.x*wq.w;
        acc1.x += xq.y*wq.x; acc1.y += xq.y*wq.y; acc1.z += xq.y*wq.z; acc1.w += xq.y*wq.w;
        acc2.x += xq.z*wq.x; acc2.y += xq.z*wq.y; acc2.z += xq.z*wq.z; acc2.w += xq.z*wq.w;
        acc3.x += xq.w*wq.x; acc3.y += xq.w*wq.y; acc3.z += xq.w*wq.z; acc3.w += xq.w*wq.w;
    }
    int n = n4*4;
    float s0 = g_invs[bn0+n], s1 = g_invs[bn0+n+1], s2 = g_invs[bn0+n+2], s3 = g_invs[bn0+n+3];
    acc0.x*=s0; acc0.y*=s0; acc0.z*=s0; acc0.w*=s0;
    acc1.x*=s1; acc1.y*=s1; acc1.z*=s1; acc1.w*=s1;
    acc2.x*=s2; acc2.y*=s2; acc2.z*=s2; acc2.w*=s2;
    acc3.x*=s3; acc3.y*=s3; acc3.z*=s3; acc3.w*=s3;
    uint2* A2 = (uint2*)g_A;
    A2[(bn0+n+0)*16 + h4] = pack_bf16x4(acc0);
    A2[(bn0+n+1)*16 + h4] = pack_bf16x4(acc1);
    A2[(bn0+n+2)*16 + h4] = pack_bf16x4(acc2);
    A2[(bn0+n+3)*16 + h4] = pack_bf16x4(acc3);
}

// ---- gather core: warp handles one node; lanes 0-15 edge j, 16-31 edge j+1 -
__device__ __forceinline__ float4 gather_node(int bn, int l16, int half)
{
    const uint2* A2 = (const uint2*)g_A;
    int cnt = g_indeg[bn];
    int off = g_off[bn];
    float4 acc = make_float4(0.f, 0.f, 0.f, 0.f);
    int e = 0;
    for (; e + 8 <= cnt; e += 8) {
        int i0 = __ldg(&g_csr[off + e     + half]);
        int i1 = __ldg(&g_csr[off + e + 2 + half]);
        int i2 = __ldg(&g_csr[off + e + 4 + half]);
        int i3 = __ldg(&g_csr[off + e + 6 + half]);
        uint2 v0 = __ldg(&A2[i0*16 + l16]);
        uint2 v1 = __ldg(&A2[i1*16 + l16]);
        uint2 v2 = __ldg(&A2[i2*16 + l16]);
        uint2 v3 = __ldg(&A2[i3*16 + l16]);
        acc_bf16x4(acc, v0); acc_bf16x4(acc, v1);
        acc_bf16x4(acc, v2); acc_bf16x4(acc, v3);
    }
    for (; e + 2 <= cnt; e += 2) {
        int i0 = __ldg(&g_csr[off + e + half]);
        uint2 v0 = __ldg(&A2[i0*16 + l16]);
        acc_bf16x4(acc, v0);
    }
    if (e < cnt && half == 0) {
        int i0 = __ldg(&g_csr[off + e]);
        uint2 v0 = __ldg(&A2[i0*16 + l16]);
        acc_bf16x4(acc, v0);
    }
    // combine the two half-warp partial sums (all lanes participate)
    acc.x += __shfl_xor_sync(0xffffffffu, acc.x, 16);
    acc.y += __shfl_xor_sync(0xffffffffu, acc.y, 16);
    acc.z += __shfl_xor_sync(0xffffffffu, acc.z, 16);
    acc.w += __shfl_xor_sync(0xffffffffu, acc.w, 16);
    return acc;
}

// ------- aggregation layer 1: gather bf16 rows + tokens + self + lrelu ------
__global__ void agg1_kernel(const float* __restrict__ b1)
{
    __shared__ float4 st[Tt*16];
    __shared__ float4 bias[16];
    int tid = threadIdx.x;
    const float4* s1p = (const float4*)g_st1;
    for (int i = tid; i < Tt*16; i += 256) st[i] = s1p[i];
    if (tid < 16) bias[tid] = ((const float4*)b1)[tid];
    __syncthreads();
    int lane = tid & 31;
    int l16 = lane & 15, half = lane >> 4;
    int bn = blockIdx.x*8 + (tid >> 5);
    float4 acc = gather_node(bn, l16, half);
    if (half == 0) {
        unsigned mk = g_mask[bn];
        while (mk) {
            int t = __ffs(mk) - 1; mk &= mk - 1;
            float4 v = st[t*16 + l16];
            acc.x += v.x; acc.y += v.y; acc.z += v.z; acc.w += v.w;
        }
        uint2 sv = ((const uint2*)g_A)[bn*16 + l16];
        acc_bf16x4(acc, sv);
        float is = g_invs[bn];
        float4 bb = bias[l16];
        float4 o;
        o.x = acc.x*is + bb.x; o.y = acc.y*is + bb.y;
        o.z = acc.z*is + bb.z; o.w = acc.w*is + bb.w;
        o.x = (o.x >= 0.f) ? o.x : 0.01f*o.x;
        o.y = (o.y >= 0.f) ? o.y : 0.01f*o.y;
        o.z = (o.z >= 0.f) ? o.z : 0.01f*o.z;
        o.w = (o.w >= 0.f) ? o.w : 0.01f*o.w;
        ((float4*)g_Bf)[bn*16 + l16] = o;
    }
}

// ------- aggregation layer 2 + mean-pool accumulation -----------------------
__global__ void agg2_kernel(const float* __restrict__ b2)
{
    __shared__ float4 st[Tt*16];
    __shared__ float4 bias[16];
    __shared__ float sum[Hh];
    int tid = threadIdx.x;
    const float4* s2p = (const float4*)g_st2;
    for (int i = tid; i < Tt*16; i += 256) st[i] = s2p[i];
    if (tid < 16) bias[tid] = ((const float4*)b2)[tid];
    if (tid < Hh) sum[tid] = 0.f;
    __syncthreads();
    int lane = tid & 31;
    int l16 = lane & 15, half = lane >> 4;
    int bn = blockIdx.x*8 + (tid >> 5);
    float4 acc = gather_node(bn, l16, half);
    if (half == 0) {
        unsigned mk = g_mask[bn];
        while (mk) {
            int t = __ffs(mk) - 1; mk &= mk - 1;
            float4 v = st[t*16 + l16];
            acc.x += v.x; acc.y += v.y; acc.z += v.z; acc.w += v.w;
        }
        uint2 sv = ((const uint2*)g_A)[bn*16 + l16];
        acc_bf16x4(acc, sv);
        float is = g_invs[bn];
        float4 bb = bias[l16];
        atomicAdd(&sum[l16*4+0], acc.x*is + bb.x);
        atomicAdd(&sum[l16*4+1], acc.y*is + bb.y);
        atomicAdd(&sum[l16*4+2], acc.z*is + bb.z);
        atomicAdd(&sum[l16*4+3], acc.w*is + bb.w);
    }
    __syncthreads();
    if (tid < Hh) {
        int b = blockIdx.x >> 7;            // 128 blocks per graph
        atomicAdd(&g_emb[b*Hh + tid], sum[tid]);
    }
}

// ---------------- answering head + softmax ----------------------------------
__global__ void head_kernel(const float* __restrict__ Wa, const float* __restrict__ ba,
                            float* __restrict__ out)
{
    int b = threadIdx.x;
    const float scale = 1.f/(float)(Tt + Nn);
    float l0 = ba[0], l1 = ba[1];
    for (int o = 0; o < Hh; o++) {
        float e = (g_emb[b*Hh + o] + g_toksum[o]) * scale;
        l0 += e*Wa[o*2+0];
        l1 += e*Wa[o*2+1];
    }
    float mx = fmaxf(l0, l1);
    float e0 = expf(l0 - mx), e1 = expf(l1 - mx);
    float s = e0 + e1;
    out[b*2+0] = e0/s;
    out[b*2+1] = e1/s;
}

// ---------------- launch ----------------------------------------------------
extern "C" void kernel_launch(void* const* d_in, const int* in_sizes, int n_in,
                              void* d_out, int out_size)
{
    const float* x    = (const float*)d_in[0];
    const float* tok  = (const float*)d_in[1];
    const float* W1   = (const float*)d_in[2];
    const float* b1   = (const float*)d_in[3];
    const float* W2   = (const float*)d_in[4];
    const float* b2   = (const float*)d_in[5];
    const float* Wa   = (const float*)d_in[6];
    const float* ba   = (const float*)d_in[7];
    const int*   esrc = (const int*)d_in[8];
    const int*   edst = (const int*)d_in[9];
    float* out = (float*)d_out;

    csr_token_kernel<<<Bq + 1, Nn>>>(esrc, edst, tok, W1, b1, W2, b2);
    xpass_kernel<<<BN/64, 256>>>(x, W1, tok);
    agg1_kernel<<<BN/8, 256>>>(b1);
    gemm64_kernel<<<BN/64, 256>>>(W2);
    agg2_kernel<<<BN/8, 256>>>(b2);
    head_kernel<<<1, Bq>>>(Wa, ba, out);
}

// round 4
// speedup vs baseline: 1.4359x; 1.2433x over previous
#include <cuda_runtime.h>
#include <cuda_bf16.h>
#include <math.h>

#define Bq 64
#define Nn 1024
#define Ee 16384
#define Ff 128
#define Hh 64
#define Tt 10
#define BN (Bq*Nn)   // 65536

// ---------------- scratch (static device globals; no allocs allowed) --------
__device__ __nv_bfloat16 g_A[BN*Hh]; // layer1: bf16 invs[n]*(x@W1)[n]
__device__ __nv_bfloat16 g_B[BN*Hh]; // layer2 gather space: bf16 invs[n]*act1[n]
__device__ int      g_csr[Bq*Ee];    // CSR-by-dst: global src ids
__device__ int      g_off[BN];       // absolute start offset into g_csr
__device__ int      g_indeg[BN];
__device__ unsigned g_mask[BN];      // 10-bit token->node mask
__device__ float    g_invs[BN];      // 1/sqrt(deg_node)
__device__ float    g_st1[Tt*Hh];    // invsT[t] * (tokens@W1)[t,:]   (layer1 cross)
__device__ float    g_st2p[Tt*Hh];   // invsT[t] * h1a_tok[t,:]       (layer2 cross, pre-W2)
__device__ float    g_toksum[Hh];    // sum_t out_tok2[t,:]
__device__ float    g_P[Bq*Hh];      // pooled pre-W2 node vectors (atomic accum)

// ---- helpers ----------------------------------------------------------------
__device__ __forceinline__ void acc_bf16x4(float4& a, uint2 v) {
    __nv_bfloat162 p0 = *reinterpret_cast<__nv_bfloat162*>(&v.x);
    __nv_bfloat162 p1 = *reinterpret_cast<__nv_bfloat162*>(&v.y);
    float2 f0 = __bfloat1622float2(p0);
    float2 f1 = __bfloat1622float2(p1);
    a.x += f0.x; a.y += f0.y; a.z += f1.x; a.w += f1.y;
}
__device__ __forceinline__ uint2 pack_bf16x4(float4 a) {
    __nv_bfloat162 lo = __float22bfloat162_rn(make_float2(a.x, a.y));
    __nv_bfloat162 hi = __float22bfloat162_rn(make_float2(a.z, a.w));
    uint2 r;
    r.x = *reinterpret_cast<unsigned*>(&lo);
    r.y = *reinterpret_cast<unsigned*>(&hi);
    return r;
}

// ---------------- CSR build (blocks 0-63) + token stream (block 64) ---------
__global__ void csr_token_kernel(const int* __restrict__ esrc, const int* __restrict__ edst,
                                 const float* __restrict__ tok,
                                 const float* __restrict__ W1, const float* __restrict__ b1,
                                 const float* __restrict__ W2, const float* __restrict__ b2)
{
    __shared__ union {
        struct { int cnt[Nn]; int wsum[32]; } c;
        struct {
            float tk[Tt][129];
            float nrm[Tt][Tt];
            float invsT[Tt], invdT[Tt];
            float h1l[Tt][Hh], h1a[Tt][Hh], h2l[Tt][Hh], ot2[Tt][Hh];
        } t;
    } u;
    int tid = threadIdx.x;

    if (blockIdx.x < Bq) {
        // ---------------- CSR build: count + scan + scatter -----------------
        int b = blockIdx.x;
        int lane = tid & 31, wid = tid >> 5;
        u.c.cnt[tid] = 0;
        __syncthreads();
        const int* dp = edst + b*Ee;
        const int* sp = esrc + b*Ee;
        for (int e = tid; e < Ee; e += Nn) atomicAdd(&u.c.cnt[dp[e]], 1);
        __syncthreads();
        int c = u.c.cnt[tid];
        g_indeg[b*Nn + tid] = c;
        int v = c;
        for (int d = 1; d < 32; d <<= 1) {
            int uu = __shfl_up_sync(0xffffffffu, v, d);
            if (lane >= d) v += uu;
        }
        if (lane == 31) u.c.wsum[wid] = v;
        __syncthreads();
        if (tid < 32) {
            int s = u.c.wsum[tid];
            for (int d = 1; d < 32; d <<= 1) {
                int uu = __shfl_up_sync(0xffffffffu, s, d);
                if (tid >= d) s += uu;
            }
            u.c.wsum[tid] = s;
        }
        __syncthreads();
        int base = wid ? u.c.wsum[wid-1] : 0;
        int pos0 = b*Ee + base + (v - c);
        g_off[b*Nn + tid] = pos0;
        __syncthreads();
        u.c.cnt[tid] = pos0;
        __syncthreads();
        for (int e = tid; e < Ee; e += Nn) {
            int d = dp[e];
            int p = atomicAdd(&u.c.cnt[d], 1);
            g_csr[p] = b*Nn + sp[e];
        }
    } else {
        // ---------------- token stream (T=10) -------------------------------
        const int NT = 1024;
        for (int i = tid; i < Tt*Ff; i += NT) u.t.tk[i/Ff][i%Ff] = tok[i];
        __syncthreads();
        if (tid < Tt*Tt) {
            int i = tid/Tt, j = tid%Tt;
            float d = 0.f;
            for (int f = 0; f < Ff; f++) d += u.t.tk[i][f]*u.t.tk[j][f];
            float s = 1.f/(1.f+expf(-d));
            u.t.nrm[i][j] = (s >= 0.3f) ? 1.f : 0.f;
        }
        __syncthreads();
        if (tid < Tt) {
            float deg = 1.f;
            for (int i = 0; i < Tt; i++) deg += u.t.nrm[i][tid];
            u.t.invsT[tid] = rsqrtf(deg);
            u.t.invdT[tid] = 1.f/deg;
        }
        __syncthreads();
        if (tid < Tt*Tt) {
            int i = tid/Tt, j = tid%Tt;
            u.t.nrm[i][j] *= u.t.invsT[i]*u.t.invsT[j];
        }
        for (int idx = tid; idx < Tt*Hh; idx += NT) {
            int t = idx/Hh, h = idx%Hh;
            float a = 0.f;
            for (int f = 0; f < Ff; f++) a += u.t.tk[t][f]*W1[f*Hh+h];
            u.t.h1l[t][h] = a;
        }
        __syncthreads();
        for (int idx = tid; idx < Tt*Hh; idx += NT) {
            int t = idx/Hh, h = idx%Hh;
            float a = u.t.h1l[t][h]*u.t.invdT[t] + b1[h];
            for (int j = 0; j < Tt; j++) a += u.t.nrm[t][j]*u.t.h1l[j][h];
            float act = (a >= 0.f) ? a : 0.01f*a;
            u.t.h1a[t][h] = act;
            g_st1[idx]  = u.t.invsT[t]*u.t.h1l[t][h];
            g_st2p[idx] = u.t.invsT[t]*act;          // pre-W2 layer-2 cross vector
        }
        __syncthreads();
        for (int idx = tid; idx < Tt*Hh; idx += NT) {
            int t = idx/Hh, h = idx%Hh;
            float a = 0.f;
            for (int k = 0; k < Hh; k++) a += u.t.h1a[t][k]*W2[k*Hh+h];
            u.t.h2l[t][h] = a;
        }
        __syncthreads();
        for (int idx = tid; idx < Tt*Hh; idx += NT) {
            int t = idx/Hh, h = idx%Hh;
            float a = u.t.h2l[t][h]*u.t.invdT[t] + b2[h];
            for (int j = 0; j < Tt; j++) a += u.t.nrm[t][j]*u.t.h2l[j][h];
            u.t.ot2[t][h] = a;
        }
        __syncthreads();
        if (tid < Hh) {
            float s = 0.f;
            for (int t = 0; t < Tt; t++) s += u.t.ot2[t][tid];
            g_toksum[tid] = s;
        }
        for (int i = tid; i < Bq*Hh; i += NT) g_P[i] = 0.f;
    }
}

// ------- fused x-pass: g_A = bf16(invs*(x@W1)), token dots -> mask, deg -----
__global__ void xpass_kernel(const float* __restrict__ x, const float* __restrict__ W1,
                             const float* __restrict__ tok)
{
    __shared__ float xs[64][68];          // transposed x chunk [f][n]
    __shared__ float ws[64][64];          // W1 chunk [f][h]
    __shared__ float ts[Tt][64];          // tokens chunk [t][f]
    __shared__ unsigned maskbuf[64];
    __shared__ float invsS[64];
    int tid = threadIdx.x;
    int bn0 = blockIdx.x * 64;
    int h4 = tid & 15, n4 = tid >> 4;

    float4 acc0 = make_float4(0.f,0.f,0.f,0.f);
    float4 acc1 = acc0, acc2 = acc0, acc3 = acc0;
    float dacc[3] = {0.f, 0.f, 0.f};
    if (tid < 64) maskbuf[tid] = 0u;

    for (int c = 0; c < 2; c++) {
        __syncthreads();
        for (int idx = tid; idx < 4096; idx += 256) {
            int f = idx & 63, n = idx >> 6;
            xs[f][n] = x[(bn0+n)*Ff + c*64 + f];
        }
        for (int idx = tid; idx < 4096; idx += 256) {
            int h = idx & 63, f = idx >> 6;
            ws[f][h] = W1[(c*64+f)*Hh + h];
        }
        for (int idx = tid; idx < Tt*64; idx += 256) {
            int f = idx & 63, t = idx >> 6;
            ts[t][f] = tok[t*Ff + c*64 + f];
        }
        __syncthreads();
        #pragma unroll 8
        for (int f = 0; f < 64; f++) {
            float4 xq = *(const float4*)&xs[f][n4*4];
            float4 wq = *(const float4*)&ws[f][h4*4];
            acc0.x += xq.x*wq.x; acc0.y += xq.x*wq.y; acc0.z += xq.x*wq.z; acc0.w += xq.x*wq.w;
            acc1.x += xq.y*wq.x; acc1.y += xq.y*wq.y; acc1.z += xq.y*wq.z; acc1.w += xq.y*wq.w;
            acc2.x += xq.z*wq.x; acc2.y += xq.z*wq.y; acc2.z += xq.z*wq.z; acc2.w += xq.z*wq.w;
            acc3.x += xq.w*wq.x; acc3.y += xq.w*wq.y; acc3.z += xq.w*wq.z; acc3.w += xq.w*wq.w;
        }
        #pragma unroll
        for (int r = 0; r < 3; r++) {
            int idx = tid + r*256;
            if (idx < 640) {
                int n = idx & 63, t = idx >> 6;
                float a = dacc[r];
                #pragma unroll 8
                for (int f = 0; f < 64; f++) a += xs[f][n]*ts[t][f];
                dacc[r] = a;
            }
        }
    }
    #pragma unroll
    for (int r = 0; r < 3; r++) {
        int idx = tid + r*256;
        if (idx < 640) {
            int n = idx & 63, t = idx >> 6;
            float s = 1.f/(1.f+expf(-dacc[r]));
            if (s >= 0.1f) atomicOr(&maskbuf[n], 1u << t);
        }
    }
    __syncthreads();
    if (tid < 64) {
        int bn = bn0 + tid;
        unsigned m = maskbuf[tid];
        float deg = 1.0f + (float)g_indeg[bn] + (float)__popc(m);
        float is = rsqrtf(deg);
        g_mask[bn] = m;
        g_invs[bn] = is;
        invsS[tid] = is;
    }
    __syncthreads();
    {
        int n = n4*4;
        float s0 = invsS[n], s1 = invsS[n+1], s2 = invsS[n+2], s3 = invsS[n+3];
        acc0.x*=s0; acc0.y*=s0; acc0.z*=s0; acc0.w*=s0;
        acc1.x*=s1; acc1.y*=s1; acc1.z*=s1; acc1.w*=s1;
        acc2.x*=s2; acc2.y*=s2; acc2.z*=s2; acc2.w*=s2;
        acc3.x*=s3; acc3.y*=s3; acc3.z*=s3; acc3.w*=s3;
        uint2* A2 = (uint2*)g_A;
        A2[(bn0+n+0)*16 + h4] = pack_bf16x4(acc0);
        A2[(bn0+n+1)*16 + h4] = pack_bf16x4(acc1);
        A2[(bn0+n+2)*16 + h4] = pack_bf16x4(acc2);
        A2[(bn0+n+3)*16 + h4] = pack_bf16x4(acc3);
    }
}

// ---- gather core: warp handles one node; lanes 0-15 edge j, 16-31 edge j+1 -
__device__ __forceinline__ float4 gather_node(const uint2* __restrict__ A2,
                                              int bn, int l16, int half)
{
    int cnt = g_indeg[bn];
    int off = g_off[bn];
    float4 acc = make_float4(0.f, 0.f, 0.f, 0.f);
    int e = 0;
    for (; e + 8 <= cnt; e += 8) {
        int i0 = __ldg(&g_csr[off + e     + half]);
        int i1 = __ldg(&g_csr[off + e + 2 + half]);
        int i2 = __ldg(&g_csr[off + e + 4 + half]);
        int i3 = __ldg(&g_csr[off + e + 6 + half]);
        uint2 v0 = __ldg(&A2[i0*16 + l16]);
        uint2 v1 = __ldg(&A2[i1*16 + l16]);
        uint2 v2 = __ldg(&A2[i2*16 + l16]);
        uint2 v3 = __ldg(&A2[i3*16 + l16]);
        acc_bf16x4(acc, v0); acc_bf16x4(acc, v1);
        acc_bf16x4(acc, v2); acc_bf16x4(acc, v3);
    }
    for (; e + 2 <= cnt; e += 2) {
        int i0 = __ldg(&g_csr[off + e + half]);
        uint2 v0 = __ldg(&A2[i0*16 + l16]);
        acc_bf16x4(acc, v0);
    }
    if (e < cnt && half == 0) {
        int i0 = __ldg(&g_csr[off + e]);
        uint2 v0 = __ldg(&A2[i0*16 + l16]);
        acc_bf16x4(acc, v0);
    }
    acc.x += __shfl_xor_sync(0xffffffffu, acc.x, 16);
    acc.y += __shfl_xor_sync(0xffffffffu, acc.y, 16);
    acc.z += __shfl_xor_sync(0xffffffffu, acc.z, 16);
    acc.w += __shfl_xor_sync(0xffffffffu, acc.w, 16);
    return acc;
}

// ------- aggregation layer 1: gather + tokens + self + lrelu -> bf16 --------
__global__ void agg1_kernel(const float* __restrict__ b1)
{
    __shared__ float4 st[Tt*16];
    __shared__ float4 bias[16];
    int tid = threadIdx.x;
    const float4* s1p = (const float4*)g_st1;
    for (int i = tid; i < Tt*16; i += 256) st[i] = s1p[i];
    if (tid < 16) bias[tid] = ((const float4*)b1)[tid];
    __syncthreads();
    int lane = tid & 31;
    int l16 = lane & 15, half = lane >> 4;
    int bn = blockIdx.x*8 + (tid >> 5);
    float4 acc = gather_node((const uint2*)g_A, bn, l16, half);
    if (half == 0) {
        unsigned mk = g_mask[bn];
        while (mk) {
            int t = __ffs(mk) - 1; mk &= mk - 1;
            float4 v = st[t*16 + l16];
            acc.x += v.x; acc.y += v.y; acc.z += v.z; acc.w += v.w;
        }
        uint2 sv = ((const uint2*)g_A)[bn*16 + l16];
        acc_bf16x4(acc, sv);
        float is = g_invs[bn];
        float4 bb = bias[l16];
        float4 o;
        o.x = acc.x*is + bb.x; o.y = acc.y*is + bb.y;
        o.z = acc.z*is + bb.z; o.w = acc.w*is + bb.w;
        o.x = (o.x >= 0.f) ? o.x : 0.01f*o.x;
        o.y = (o.y >= 0.f) ? o.y : 0.01f*o.y;
        o.z = (o.z >= 0.f) ? o.z : 0.01f*o.z;
        o.w = (o.w >= 0.f) ? o.w : 0.01f*o.w;
        // store invs * act1 directly in bf16 (gather space for layer 2)
        o.x *= is; o.y *= is; o.z *= is; o.w *= is;
        ((uint2*)g_B)[bn*16 + l16] = pack_bf16x4(o);
    }
}

// ------- aggregation layer 2 (pre-W2 space) + per-graph pooling -------------
__global__ void agg2_kernel()
{
    __shared__ float4 st[Tt*16];
    __shared__ float sum[Hh];
    int tid = threadIdx.x;
    const float4* s2p = (const float4*)g_st2p;
    for (int i = tid; i < Tt*16; i += 256) st[i] = s2p[i];
    if (tid < Hh) sum[tid] = 0.f;
    __syncthreads();
    int lane = tid & 31;
    int l16 = lane & 15, half = lane >> 4;
    int bn = blockIdx.x*8 + (tid >> 5);
    float4 acc = gather_node((const uint2*)g_B, bn, l16, half);
    if (half == 0) {
        unsigned mk = g_mask[bn];
        while (mk) {
            int t = __ffs(mk) - 1; mk &= mk - 1;
            float4 v = st[t*16 + l16];
            acc.x += v.x; acc.y += v.y; acc.z += v.z; acc.w += v.w;
        }
        uint2 sv = ((const uint2*)g_B)[bn*16 + l16];
        acc_bf16x4(acc, sv);
        float is = g_invs[bn];
        atomicAdd(&sum[l16*4+0], acc.x*is);
        atomicAdd(&sum[l16*4+1], acc.y*is);
        atomicAdd(&sum[l16*4+2], acc.z*is);
        atomicAdd(&sum[l16*4+3], acc.w*is);
    }
    __syncthreads();
    if (tid < Hh) {
        int b = blockIdx.x >> 7;            // 128 blocks per graph
        atomicAdd(&g_P[b*Hh + tid], sum[tid]);
    }
}

// ------- head: per-graph W2 matvec + b2 + toksum, pool, answering, softmax --
__global__ void head_kernel(const float* __restrict__ W2, const float* __restrict__ b2,
                            const float* __restrict__ Wa, const float* __restrict__ ba,
                            float* __restrict__ out)
{
    __shared__ float P[Hh];
    __shared__ float emb[Hh];
    int g = blockIdx.x, h = threadIdx.x;
    P[h] = g_P[g*Hh + h];
    __syncthreads();
    const float scale = 1.f/(float)(Tt + Nn);
    float a = 0.f;
    for (int k = 0; k < Hh; k++) a += P[k]*W2[k*Hh + h];
    // sum over nodes of out2 = P@W2 + N*b2 ; add token-side sum; mean-pool
    emb[h] = (a + (float)Nn*b2[h] + g_toksum[h]) * scale;
    __syncthreads();
    if (h == 0) {
        float l0 = ba[0], l1 = ba[1];
        for (int o = 0; o < Hh; o++) {
            l0 += emb[o]*Wa[o*2+0];
            l1 += emb[o]*Wa[o*2+1];
        }
        float mx = fmaxf(l0, l1);
        float e0 = expf(l0 - mx), e1 = expf(l1 - mx);
        float s = e0 + e1;
        out[g*2+0] = e0/s;
        out[g*2+1] = e1/s;
    }
}

// ---------------- launch ----------------------------------------------------
extern "C" void kernel_launch(void* const* d_in, const int* in_sizes, int n_in,
                              void* d_out, int out_size)
{
    const float* x    = (const float*)d_in[0];
    const float* tok  = (const float*)d_in[1];
    const float* W1   = (const float*)d_in[2];
    const float* b1   = (const float*)d_in[3];
    const float* W2   = (const float*)d_in[4];
    const float* b2   = (const float*)d_in[5];
    const float* Wa   = (const float*)d_in[6];
    const float* ba   = (const float*)d_in[7];
    const int*   esrc = (const int*)d_in[8];
    const int*   edst = (const int*)d_in[9];
    float* out = (float*)d_out;

    csr_token_kernel<<<Bq + 1, Nn>>>(esrc, edst, tok, W1, b1, W2, b2);
    xpass_kernel<<<BN/64, 256>>>(x, W1, tok);
    agg1_kernel<<<BN/8, 256>>>(b1);
    agg2_kernel<<<BN/8, 256>>>();
    head_kernel<<<Bq, Hh>>>(W2, b2, Wa, ba, out);
}